// round 1
// baseline (speedup 1.0000x reference)
#include <cuda_runtime.h>

#define BB 4096
#define TT 2048
#define HH 10

__device__ __forceinline__ float sigmoidf_(float x) {
    // 1/(1+e^-x) via EX2 + RCP (MUFU), ~1e-7 rel err
    return __fdividef(1.0f, 1.0f + __expf(-x));
}
__device__ __forceinline__ float tanhf_(float x) {
    // 2*sigmoid(2x) - 1
    return fmaf(2.0f, __fdividef(1.0f, 1.0f + __expf(-2.0f * x)), -1.0f);
}

// One hidden unit per thread, 3 LSTM batch elements per warp (lanes 0..29).
// h/c live in registers; h is exchanged within the warp via shfl each step.
__global__ void __launch_bounds__(128) lstm_fused_kernel(
    const float* __restrict__ x,      // [B, T, 1]
    const float* __restrict__ W_ih,   // [4H, 1]
    const float* __restrict__ W_hh,   // [4H, H]
    const float* __restrict__ b_ih,   // [4H]
    const float* __restrict__ b_hh,   // [4H]
    const float* __restrict__ W_out,  // [1, H]
    const float* __restrict__ b_out,  // [1]
    float* __restrict__ out)          // [B, T, 1]
{
    const int lane = threadIdx.x & 31;
    const int warp = (blockIdx.x * blockDim.x + threadIdx.x) >> 5;

    int ew = lane / HH;              // element-within-warp: 0..2 (3 = idle lanes 30,31)
    int j  = lane - ew * HH;         // hidden unit 0..9
    bool active = (ew < 3);
    int base = ew * HH;              // shfl source base for this element
    if (!active) { base = 0; j = 0; }

    int b = warp * 3 + ew;
    if (b >= BB) active = false;
    const int bb = active ? b : 0;   // clamp for safe (unused) loads

    // ---- per-thread constants: this unit's recurrent weight rows ----
    float wi[HH], wf[HH], wg[HH], wo[HH], wout[HH];
#pragma unroll
    for (int k = 0; k < HH; k++) {
        wi[k]   = W_hh[(0 * HH + j) * HH + k];
        wf[k]   = W_hh[(1 * HH + j) * HH + k];
        wg[k]   = W_hh[(2 * HH + j) * HH + k];
        wo[k]   = W_hh[(3 * HH + j) * HH + k];
        wout[k] = W_out[k];
    }
    const float wxi = W_ih[0 * HH + j];
    const float wxf = W_ih[1 * HH + j];
    const float wxg = W_ih[2 * HH + j];
    const float wxo = W_ih[3 * HH + j];
    const float bi = b_ih[0 * HH + j] + b_hh[0 * HH + j];
    const float bf = b_ih[1 * HH + j] + b_hh[1 * HH + j];
    const float bg = b_ih[2 * HH + j] + b_hh[2 * HH + j];
    const float bo = b_ih[3 * HH + j] + b_hh[3 * HH + j];
    const float bout = b_out[0];

    const float* xp = x   + (size_t)bb * TT;
    float*       op = out + (size_t)bb * TT;
    const bool do_out = active && (j == 0);

    float h = 0.0f, c = 0.0f;
    float xv = xp[0];

    for (int t = 0; t < TT; t++) {
        // gather h[t-1] for this element (zeros at t=0)
        float hh[HH];
#pragma unroll
        for (int k = 0; k < HH; k++)
            hh[k] = __shfl_sync(0xffffffffu, h, base + k);

        // output for step t-1 (h[t-1] = hh); computed redundantly, stored by j==0
        float o_acc = bout;
#pragma unroll
        for (int k = 0; k < HH; k++) o_acc = fmaf(hh[k], wout[k], o_acc);
        if (do_out && t > 0) op[t - 1] = o_acc;

        // prefetch next x while gates compute
        float xn = xp[(t + 1 < TT) ? (t + 1) : t];

        // gate pre-activations
        float ai = fmaf(xv, wxi, bi);
        float af = fmaf(xv, wxf, bf);
        float ag = fmaf(xv, wxg, bg);
        float ao = fmaf(xv, wxo, bo);
#pragma unroll
        for (int k = 0; k < HH; k++) {
            ai = fmaf(hh[k], wi[k], ai);
            af = fmaf(hh[k], wf[k], af);
            ag = fmaf(hh[k], wg[k], ag);
            ao = fmaf(hh[k], wo[k], ao);
        }
        float ig = sigmoidf_(ai);
        float fg = sigmoidf_(af);
        float gg = tanhf_(ag);
        float og = sigmoidf_(ao);
        c = fmaf(fg, c, ig * gg);
        h = og * tanhf_(c);
        xv = xn;
    }

    // final output: t = T-1 from the last h
    {
        float hh[HH];
#pragma unroll
        for (int k = 0; k < HH; k++)
            hh[k] = __shfl_sync(0xffffffffu, h, base + k);
        float o_acc = bout;
#pragma unroll
        for (int k = 0; k < HH; k++) o_acc = fmaf(hh[k], wout[k], o_acc);
        if (do_out) op[TT - 1] = o_acc;
    }
}

extern "C" void kernel_launch(void* const* d_in, const int* in_sizes, int n_in,
                              void* d_out, int out_size) {
    const float* x     = (const float*)d_in[0];
    const float* W_ih  = (const float*)d_in[1];
    const float* W_hh  = (const float*)d_in[2];
    const float* b_ih  = (const float*)d_in[3];
    const float* b_hh  = (const float*)d_in[4];
    const float* W_out = (const float*)d_in[5];
    const float* b_out = (const float*)d_in[6];
    float* out = (float*)d_out;

    // 3 elements per warp, 4 warps (12 elements) per 128-thread block
    const int elems_per_block = 12;
    const int grid = (BB + elems_per_block - 1) / elems_per_block;  // 342
    lstm_fused_kernel<<<grid, 128>>>(x, W_ih, W_hh, b_ih, b_hh, W_out, b_out, out);
}

// round 2
// speedup vs baseline: 1.3362x; 1.3362x over previous
#include <cuda_runtime.h>

#define BB 4096
#define TT 2048
#define HH 10

union F2U { float2 f; unsigned long long u; };

__device__ __forceinline__ float2 ffma2(float2 a, float2 b, float2 c) {
    F2U ua, ub, uc, ud;
    ua.f = a; ub.f = b; uc.f = c;
    asm("fma.rn.f32x2 %0, %1, %2, %3;" : "=l"(ud.u) : "l"(ua.u), "l"(ub.u), "l"(uc.u));
    return ud.f;
}

__device__ __forceinline__ float tanh_fast(float x) {
    float y;
    asm("tanh.approx.f32 %0, %1;" : "=f"(y) : "f"(x));
    return y;
}

// One hidden unit per thread, 3 LSTM batch elements per warp (lanes 0..29).
// h/c in registers; h exchanged via shfl. Gates use f32x2 packed FMA chains
// (even/odd k split -> depth 5), activations via MUFU.TANH with the sigmoid
// 0.5-scale folded into pre-scaled weights/biases.
__global__ void __launch_bounds__(128) lstm_fused_kernel(
    const float* __restrict__ x,      // [B, T, 1]
    const float* __restrict__ W_ih,   // [4H, 1]
    const float* __restrict__ W_hh,   // [4H, H]
    const float* __restrict__ b_ih,   // [4H]
    const float* __restrict__ b_hh,   // [4H]
    const float* __restrict__ W_out,  // [1, H]
    const float* __restrict__ b_out,  // [1]
    float* __restrict__ out)          // [B, T, 1]
{
    const int lane = threadIdx.x & 31;
    const int warp = (blockIdx.x * blockDim.x + threadIdx.x) >> 5;

    int ew = lane / HH;              // element-within-warp: 0..2 (lanes 30,31 idle)
    int j  = lane - ew * HH;         // hidden unit 0..9
    bool active = (ew < 3);
    int base = ew * HH;
    if (!active) { base = 0; j = 0; }

    int b = warp * 3 + ew;
    if (b >= BB) active = false;
    const int bb = active ? b : 0;

    // ---- per-thread constants ----
    // sigmoid gates (i,f,o): weights & biases pre-scaled by 0.5 so
    // sigmoid(a) = 0.5*tanh(0.5*a) + 0.5 needs no extra scale on a.
    float2 wi2[5], wf2[5], wg2[5], wo2[5], wout2[5];
#pragma unroll
    for (int m = 0; m < 5; m++) {
        wi2[m] = make_float2(0.5f * W_hh[(0 * HH + j) * HH + 2 * m],
                             0.5f * W_hh[(0 * HH + j) * HH + 2 * m + 1]);
        wf2[m] = make_float2(0.5f * W_hh[(1 * HH + j) * HH + 2 * m],
                             0.5f * W_hh[(1 * HH + j) * HH + 2 * m + 1]);
        wg2[m] = make_float2(W_hh[(2 * HH + j) * HH + 2 * m],
                             W_hh[(2 * HH + j) * HH + 2 * m + 1]);
        wo2[m] = make_float2(0.5f * W_hh[(3 * HH + j) * HH + 2 * m],
                             0.5f * W_hh[(3 * HH + j) * HH + 2 * m + 1]);
        wout2[m] = make_float2(W_out[2 * m], W_out[2 * m + 1]);
    }
    const float wxi = 0.5f * W_ih[0 * HH + j];
    const float wxf = 0.5f * W_ih[1 * HH + j];
    const float wxg =        W_ih[2 * HH + j];
    const float wxo = 0.5f * W_ih[3 * HH + j];
    const float bi = 0.5f * (b_ih[0 * HH + j] + b_hh[0 * HH + j]);
    const float bf = 0.5f * (b_ih[1 * HH + j] + b_hh[1 * HH + j]);
    const float bg =        (b_ih[2 * HH + j] + b_hh[2 * HH + j]);
    const float bo = 0.5f * (b_ih[3 * HH + j] + b_hh[3 * HH + j]);
    const float bout = b_out[0];

    const float* xp = x   + (size_t)bb * TT;
    float*       op = out + (size_t)bb * TT;
    const bool do_out = active && (j == 0);

    float h = 0.0f, c = 0.0f;
    float xv = xp[0];

#pragma unroll 2
    for (int t = 0; t < TT; t++) {
        // gather h[t-1] for this element into aligned float2 pairs
        float2 hh2[5];
#pragma unroll
        for (int m = 0; m < 5; m++) {
            hh2[m].x = __shfl_sync(0xffffffffu, h, base + 2 * m);
            hh2[m].y = __shfl_sync(0xffffffffu, h, base + 2 * m + 1);
        }

        // output for step t-1 (uses h[t-1] = hh2); stored by j==0 lanes
        float2 oacc = make_float2(bout, 0.0f);
#pragma unroll
        for (int m = 0; m < 5; m++) oacc = ffma2(hh2[m], wout2[m], oacc);
        if (do_out && t > 0) op[t - 1] = oacc.x + oacc.y;

        // prefetch next x
        float xn = xp[(t + 1 < TT) ? (t + 1) : t];

        // gate pre-activations: packed even/odd-k chains, depth 5
        float2 aI = make_float2(fmaf(xv, wxi, bi), 0.0f);
        float2 aF = make_float2(fmaf(xv, wxf, bf), 0.0f);
        float2 aG = make_float2(fmaf(xv, wxg, bg), 0.0f);
        float2 aO = make_float2(fmaf(xv, wxo, bo), 0.0f);
#pragma unroll
        for (int m = 0; m < 5; m++) {
            aI = ffma2(hh2[m], wi2[m], aI);
            aF = ffma2(hh2[m], wf2[m], aF);
            aG = ffma2(hh2[m], wg2[m], aG);
            aO = ffma2(hh2[m], wo2[m], aO);
        }
        float si = fmaf(tanh_fast(aI.x + aI.y), 0.5f, 0.5f);
        float sf = fmaf(tanh_fast(aF.x + aF.y), 0.5f, 0.5f);
        float g  =      tanh_fast(aG.x + aG.y);
        float so = fmaf(tanh_fast(aO.x + aO.y), 0.5f, 0.5f);
        c = fmaf(sf, c, si * g);
        h = so * tanh_fast(c);
        xv = xn;
    }

    // final output: t = T-1 from the last h
    {
        float2 hh2[5];
#pragma unroll
        for (int m = 0; m < 5; m++) {
            hh2[m].x = __shfl_sync(0xffffffffu, h, base + 2 * m);
            hh2[m].y = __shfl_sync(0xffffffffu, h, base + 2 * m + 1);
        }
        float2 oacc = make_float2(bout, 0.0f);
#pragma unroll
        for (int m = 0; m < 5; m++) oacc = ffma2(hh2[m], wout2[m], oacc);
        if (do_out) op[TT - 1] = oacc.x + oacc.y;
    }
}

extern "C" void kernel_launch(void* const* d_in, const int* in_sizes, int n_in,
                              void* d_out, int out_size) {
    const float* x     = (const float*)d_in[0];
    const float* W_ih  = (const float*)d_in[1];
    const float* W_hh  = (const float*)d_in[2];
    const float* b_ih  = (const float*)d_in[3];
    const float* b_hh  = (const float*)d_in[4];
    const float* W_out = (const float*)d_in[5];
    const float* b_out = (const float*)d_in[6];
    float* out = (float*)d_out;

    const int elems_per_block = 12;  // 3 per warp, 4 warps
    const int grid = (BB + elems_per_block - 1) / elems_per_block;  // 342
    lstm_fused_kernel<<<grid, 128>>>(x, W_ih, W_hh, b_ih, b_hh, W_out, b_out, out);
}

// round 3
// speedup vs baseline: 1.5247x; 1.1410x over previous
#include <cuda_runtime.h>

#define BB 4096
#define TT 2048
#define HH 10

union F2U { float2 f; unsigned long long u; };

__device__ __forceinline__ float2 ffma2(float2 a, float2 b, float2 c) {
    F2U ua, ub, uc, ud;
    ua.f = a; ub.f = b; uc.f = c;
    asm("fma.rn.f32x2 %0, %1, %2, %3;" : "=l"(ud.u) : "l"(ua.u), "l"(ub.u), "l"(uc.u));
    return ud.f;
}

__device__ __forceinline__ float tanh_fast(float x) {
    float y;
    asm("tanh.approx.f32 %0, %1;" : "=f"(y) : "f"(x));
    return y;
}

// One hidden unit per thread, 3 LSTM batch elements per warp (lanes 0..29).
// h/c in registers; h exchanged via shfl. Gates: f32x2 packed FMA chains.
// Activations: MUFU.TANH, sigmoid's 0.5-scale folded into weights/biases.
// x read as float4 once per 4 steps (software pipelined); first block peeled
// so the main loop stores unconditionally.
__global__ void __launch_bounds__(128) lstm_fused_kernel(
    const float* __restrict__ x,      // [B, T, 1]
    const float* __restrict__ W_ih,   // [4H, 1]
    const float* __restrict__ W_hh,   // [4H, H]
    const float* __restrict__ b_ih,   // [4H]
    const float* __restrict__ b_hh,   // [4H]
    const float* __restrict__ W_out,  // [1, H]
    const float* __restrict__ b_out,  // [1]
    float* __restrict__ out)          // [B, T, 1]
{
    const int lane = threadIdx.x & 31;
    const int warp = (blockIdx.x * blockDim.x + threadIdx.x) >> 5;

    int ew = lane / HH;              // element-within-warp: 0..2 (lanes 30,31 idle)
    int j  = lane - ew * HH;         // hidden unit 0..9
    bool active = (ew < 3);
    int base = ew * HH;
    if (!active) { base = 0; j = 0; }

    int b = warp * 3 + ew;
    if (b >= BB) active = false;
    const int bb = active ? b : 0;

    // ---- per-thread constants (sigmoid gates pre-scaled by 0.5) ----
    float2 wi2[5], wf2[5], wg2[5], wo2[5], wout2[5];
#pragma unroll
    for (int m = 0; m < 5; m++) {
        wi2[m] = make_float2(0.5f * W_hh[(0 * HH + j) * HH + 2 * m],
                             0.5f * W_hh[(0 * HH + j) * HH + 2 * m + 1]);
        wf2[m] = make_float2(0.5f * W_hh[(1 * HH + j) * HH + 2 * m],
                             0.5f * W_hh[(1 * HH + j) * HH + 2 * m + 1]);
        wg2[m] = make_float2(W_hh[(2 * HH + j) * HH + 2 * m],
                             W_hh[(2 * HH + j) * HH + 2 * m + 1]);
        wo2[m] = make_float2(0.5f * W_hh[(3 * HH + j) * HH + 2 * m],
                             0.5f * W_hh[(3 * HH + j) * HH + 2 * m + 1]);
        wout2[m] = make_float2(W_out[2 * m], W_out[2 * m + 1]);
    }
    const float wxi = 0.5f * W_ih[0 * HH + j];
    const float wxf = 0.5f * W_ih[1 * HH + j];
    const float wxg =        W_ih[2 * HH + j];
    const float wxo = 0.5f * W_ih[3 * HH + j];
    const float bi = 0.5f * (b_ih[0 * HH + j] + b_hh[0 * HH + j]);
    const float bf = 0.5f * (b_ih[1 * HH + j] + b_hh[1 * HH + j]);
    const float bg =        (b_ih[2 * HH + j] + b_hh[2 * HH + j]);
    const float bo = 0.5f * (b_ih[3 * HH + j] + b_hh[3 * HH + j]);
    const float bout = b_out[0];

    const float* xp = x   + (size_t)bb * TT;
    float*       op = out + (size_t)bb * TT;
    const bool do_out = active && (j == 0);

    float h = 0.0f, c = 0.0f;

    // One LSTM step. Emits out[gt-1] (projection of h[gt-1]) when store=true.
    auto step = [&](float xv, int gt, bool store) {
        float2 hh2[5];
#pragma unroll
        for (int m = 0; m < 5; m++) {
            hh2[m].x = __shfl_sync(0xffffffffu, h, base + 2 * m);
            hh2[m].y = __shfl_sync(0xffffffffu, h, base + 2 * m + 1);
        }

        float2 oacc = make_float2(bout, 0.0f);
#pragma unroll
        for (int m = 0; m < 5; m++) oacc = ffma2(hh2[m], wout2[m], oacc);
        if (store && do_out) op[gt - 1] = oacc.x + oacc.y;

        float2 aI = make_float2(fmaf(xv, wxi, bi), 0.0f);
        float2 aF = make_float2(fmaf(xv, wxf, bf), 0.0f);
        float2 aG = make_float2(fmaf(xv, wxg, bg), 0.0f);
        float2 aO = make_float2(fmaf(xv, wxo, bo), 0.0f);
#pragma unroll
        for (int m = 0; m < 5; m++) {
            aI = ffma2(hh2[m], wi2[m], aI);
            aF = ffma2(hh2[m], wf2[m], aF);
            aG = ffma2(hh2[m], wg2[m], aG);
            aO = ffma2(hh2[m], wo2[m], aO);
        }
        float si = fmaf(tanh_fast(aI.x + aI.y), 0.5f, 0.5f);
        float sf = fmaf(tanh_fast(aF.x + aF.y), 0.5f, 0.5f);
        float g  =      tanh_fast(aG.x + aG.y);
        float so = fmaf(tanh_fast(aO.x + aO.y), 0.5f, 0.5f);
        c = fmaf(sf, c, si * g);
        h = so * tanh_fast(c);
    };

    // ---- peeled first block (no store at gt=0) ----
    float4 x4 = *(const float4*)xp;
    float4 xn4 = *(const float4*)(xp + 4);
    step(x4.x, 0, false);
    step(x4.y, 1, true);
    step(x4.z, 2, true);
    step(x4.w, 3, true);
    x4 = xn4;

    // ---- main loop: blocks 1..511, always stores ----
    for (int u = 1; u < TT / 4; u++) {
        const int gt = 4 * u;
        if (u + 1 < TT / 4) xn4 = *(const float4*)(xp + 4 * u + 4);
        step(x4.x, gt + 0, true);
        step(x4.y, gt + 1, true);
        step(x4.z, gt + 2, true);
        step(x4.w, gt + 3, true);
        x4 = xn4;
    }

    // ---- final output: out[T-1] from the last h ----
    {
        float2 hh2[5];
#pragma unroll
        for (int m = 0; m < 5; m++) {
            hh2[m].x = __shfl_sync(0xffffffffu, h, base + 2 * m);
            hh2[m].y = __shfl_sync(0xffffffffu, h, base + 2 * m + 1);
        }
        float2 oacc = make_float2(bout, 0.0f);
#pragma unroll
        for (int m = 0; m < 5; m++) oacc = ffma2(hh2[m], wout2[m], oacc);
        if (do_out) op[TT - 1] = oacc.x + oacc.y;
    }
}

extern "C" void kernel_launch(void* const* d_in, const int* in_sizes, int n_in,
                              void* d_out, int out_size) {
    const float* x     = (const float*)d_in[0];
    const float* W_ih  = (const float*)d_in[1];
    const float* W_hh  = (const float*)d_in[2];
    const float* b_ih  = (const float*)d_in[3];
    const float* b_hh  = (const float*)d_in[4];
    const float* W_out = (const float*)d_in[5];
    const float* b_out = (const float*)d_in[6];
    float* out = (float*)d_out;

    const int elems_per_block = 12;  // 3 per warp, 4 warps
    const int grid = (BB + elems_per_block - 1) / elems_per_block;  // 342
    lstm_fused_kernel<<<grid, 128>>>(x, W_ih, W_hh, b_ih, b_hh, W_out, b_out, out);
}